// round 10
// baseline (speedup 1.0000x reference)
#include <cuda_runtime.h>

// Problem constants
#define B_   2
#define T_   8
#define BT_  16
#define NQ_  128
#define NK_  128
#define DIN_ 64
#define DOUT_ 256
#define DH_  128     // d-values per d-half
#define DC_  64      // d-values per staged chunk
#define KPITCH_ 68   // words per K row (68 % 32 == 4 -> conflict-free LDS.128)

// Device-global scratch: tanh of projected Q / K (fp32), + partial scores
__device__ float g_Q[B_ * NQ_ * DOUT_];       // tq = tanh(query @ Wq)
__device__ float g_K[BT_ * NK_ * DOUT_];      // tk = tanh(keys @ Wk + bk)
__device__ float g_P[2 * BT_ * NQ_ * NK_];    // partial scores per d-half (2 MB)

__device__ __forceinline__ float ftanh(float x) {
    float r;
    asm("tanh.approx.f32 %0, %1;" : "=f"(r) : "f"(x));
    return r;
}
__device__ __forceinline__ float frcp(float x) {
    float r;
    asm("rcp.approx.f32 %0, %1;" : "=f"(r) : "f"(x));
    return r;
}

// ---------------------------------------------------------------------------
// Kernel 1: projections + tanh at store (fp32).
// Grid = 32 Q + 256 K = 288 blocks (8 rows), 2 blocks/SM.
// ---------------------------------------------------------------------------
__global__ void __launch_bounds__(256, 2) proj_kernel(
    const float* __restrict__ query, const float* __restrict__ keys,
    const float* __restrict__ Wq,    const float* __restrict__ Wk,
    const float* __restrict__ bk)
{
    __shared__ float in_sh[8][DIN_];

    const int blk = blockIdx.x;            // 0..287
    const bool isQ = (blk < 32);
    const int r0 = (isQ ? blk : (blk - 32)) * 8;
    const float* __restrict__ in = isQ ? query : keys;
    const float* __restrict__ W  = isQ ? Wq    : Wk;
    float* __restrict__ outb     = isQ ? g_Q   : g_K;

    const int tid = threadIdx.x;
    const int cg = tid & 63;
    const int rg = tid >> 6;

    if (tid < 128) {
        const int r = tid >> 4, s = tid & 15;
        *(float4*)&in_sh[r][s * 4] =
            *(const float4*)(in + (size_t)(r0 + r) * DIN_ + s * 4);
    }
    __syncthreads();

    float4 bias = make_float4(0.f, 0.f, 0.f, 0.f);
    if (!isQ) bias = *(const float4*)(bk + cg * 4);

    float4 acc0 = bias, acc1 = bias;
    const int row0 = rg * 2, row1 = rg * 2 + 1;

    float4 wcur[8], wnxt[8];
#pragma unroll
    for (int i = 0; i < 8; i++)
        wcur[i] = *(const float4*)(W + (size_t)i * DOUT_ + cg * 4);

#pragma unroll
    for (int ic = 0; ic < 8; ic++) {
        if (ic < 7) {
#pragma unroll
            for (int i = 0; i < 8; i++)
                wnxt[i] = *(const float4*)(W + (size_t)((ic + 1) * 8 + i) * DOUT_ + cg * 4);
        }
#pragma unroll
        for (int i = 0; i < 8; i++) {
            const float x0 = in_sh[row0][ic * 8 + i];
            const float x1 = in_sh[row1][ic * 8 + i];
            acc0.x = fmaf(x0, wcur[i].x, acc0.x);
            acc0.y = fmaf(x0, wcur[i].y, acc0.y);
            acc0.z = fmaf(x0, wcur[i].z, acc0.z);
            acc0.w = fmaf(x0, wcur[i].w, acc0.w);
            acc1.x = fmaf(x1, wcur[i].x, acc1.x);
            acc1.y = fmaf(x1, wcur[i].y, acc1.y);
            acc1.z = fmaf(x1, wcur[i].z, acc1.z);
            acc1.w = fmaf(x1, wcur[i].w, acc1.w);
        }
#pragma unroll
        for (int i = 0; i < 8; i++) wcur[i] = wnxt[i];
    }

    float4 t0 = make_float4(ftanh(acc0.x), ftanh(acc0.y), ftanh(acc0.z), ftanh(acc0.w));
    float4 t1 = make_float4(ftanh(acc1.x), ftanh(acc1.y), ftanh(acc1.z), ftanh(acc1.w));
    *(float4*)&outb[(size_t)(r0 + row0) * DOUT_ + cg * 4] = t0;
    *(float4*)&outb[(size_t)(r0 + row1) * DOUT_ + cg * 4] = t1;
}

// ---------------------------------------------------------------------------
// Kernel 2: partial scores via tanh addition identity over a d-half.
//   tanh(q+k) = (tq + tk) * rcp(1 + tq*tk)    [exact; rcp = rt-8 MUFU]
// Per element: 4 FMA-pipe ops + 1 MUFU -> both pipes at 28.3K cyc/SMSP.
// Explicit .xyzw everywhere: NO ternaries in hot code (R9 lesson: they
// compiled to SEL chains, +4 ALU ops/elem, issue-bound at 75%).
// Grid = 16 bt x 16 qc x 2 dh = 512 blocks, 4/SM -> 32 warps/SM.
// ---------------------------------------------------------------------------
__global__ void __launch_bounds__(256, 4) attn_partial_kernel(
    const float* __restrict__ v)
{
    __shared__ float k_sh[NK_ * KPITCH_];      // 34.8 KB
    __shared__ float q_sh[8][DC_];             // 2 KB
    __shared__ float v_sh[DC_];                // 256 B

    const int blk = blockIdx.x;
    const int dh  = blk & 1;
    const int qc  = (blk >> 1) & 15;
    const int bt  = blk >> 5;
    const int b   = bt >> 3;

    const int tid  = threadIdx.x;
    const int w    = tid >> 5;
    const int lane = tid & 31;

    float accA = 0.f, accB = 0.f, accC = 0.f, accD = 0.f;

#pragma unroll 1
    for (int c = 0; c < DH_ / DC_; c++) {
        const int d0 = dh * DH_ + c * DC_;
        const float* __restrict__ kbase = g_K + (size_t)(bt * NK_) * DOUT_ + d0;
        const float* __restrict__ qbase = g_Q + (size_t)(b * NQ_ + qc * 8) * DOUT_ + d0;

#pragma unroll
        for (int e = tid; e < NK_ * 16; e += 256) {
            const int nk = e >> 4, s = e & 15;
            float4 t = *(const float4*)(kbase + (size_t)nk * DOUT_ + s * 4);
            *(float4*)&k_sh[nk * KPITCH_ + s * 4] = t;
        }
        if (tid < 128) {
            const int r = tid >> 4, s = tid & 15;
            *(float4*)&q_sh[r][s * 4] =
                *(const float4*)(qbase + (size_t)r * DOUT_ + s * 4);
        }
        if (tid >= 128 && tid < 144) {
            const int s = tid - 128;
            *(float4*)&v_sh[s * 4] = *(const float4*)(v + d0 + s * 4);
        }
        __syncthreads();

        const float* __restrict__ kAp = &k_sh[(lane      ) * KPITCH_];
        const float* __restrict__ kBp = &k_sh[(lane + 32 ) * KPITCH_];
        const float* __restrict__ kCp = &k_sh[(lane + 64 ) * KPITCH_];
        const float* __restrict__ kDp = &k_sh[(lane + 96 ) * KPITCH_];

#pragma unroll 4
        for (int d4 = 0; d4 < DC_; d4 += 4) {
            float4 kA = *(const float4*)(kAp + d4);
            float4 kB = *(const float4*)(kBp + d4);
            float4 kC = *(const float4*)(kCp + d4);
            float4 kD = *(const float4*)(kDp + d4);
            float4 qv = *(const float4*)&q_sh[w][d4];
            float4 vv = *(const float4*)&v_sh[d4];

            // --- d component x ---
            {
                const float rA = frcp(fmaf(qv.x, kA.x, 1.0f));
                const float rB = frcp(fmaf(qv.x, kB.x, 1.0f));
                const float rC = frcp(fmaf(qv.x, kC.x, 1.0f));
                const float rD = frcp(fmaf(qv.x, kD.x, 1.0f));
                accA = fmaf(vv.x * (qv.x + kA.x), rA, accA);
                accB = fmaf(vv.x * (qv.x + kB.x), rB, accB);
                accC = fmaf(vv.x * (qv.x + kC.x), rC, accC);
                accD = fmaf(vv.x * (qv.x + kD.x), rD, accD);
            }
            // --- d component y ---
            {
                const float rA = frcp(fmaf(qv.y, kA.y, 1.0f));
                const float rB = frcp(fmaf(qv.y, kB.y, 1.0f));
                const float rC = frcp(fmaf(qv.y, kC.y, 1.0f));
                const float rD = frcp(fmaf(qv.y, kD.y, 1.0f));
                accA = fmaf(vv.y * (qv.y + kA.y), rA, accA);
                accB = fmaf(vv.y * (qv.y + kB.y), rB, accB);
                accC = fmaf(vv.y * (qv.y + kC.y), rC, accC);
                accD = fmaf(vv.y * (qv.y + kD.y), rD, accD);
            }
            // --- d component z ---
            {
                const float rA = frcp(fmaf(qv.z, kA.z, 1.0f));
                const float rB = frcp(fmaf(qv.z, kB.z, 1.0f));
                const float rC = frcp(fmaf(qv.z, kC.z, 1.0f));
                const float rD = frcp(fmaf(qv.z, kD.z, 1.0f));
                accA = fmaf(vv.z * (qv.z + kA.z), rA, accA);
                accB = fmaf(vv.z * (qv.z + kB.z), rB, accB);
                accC = fmaf(vv.z * (qv.z + kC.z), rC, accC);
                accD = fmaf(vv.z * (qv.z + kD.z), rD, accD);
            }
            // --- d component w ---
            {
                const float rA = frcp(fmaf(qv.w, kA.w, 1.0f));
                const float rB = frcp(fmaf(qv.w, kB.w, 1.0f));
                const float rC = frcp(fmaf(qv.w, kC.w, 1.0f));
                const float rD = frcp(fmaf(qv.w, kD.w, 1.0f));
                accA = fmaf(vv.w * (qv.w + kA.w), rA, accA);
                accB = fmaf(vv.w * (qv.w + kB.w), rB, accB);
                accC = fmaf(vv.w * (qv.w + kC.w), rC, accC);
                accD = fmaf(vv.w * (qv.w + kD.w), rD, accD);
            }
        }
        __syncthreads();
    }

    float* __restrict__ prow =
        g_P + ((size_t)dh * BT_ * NQ_ + (size_t)(bt * NQ_ + qc * 8 + w)) * NK_;
    prow[lane      ] = accA;
    prow[lane + 32 ] = accB;
    prow[lane + 64 ] = accC;
    prow[lane + 96 ] = accD;
}

// ---------------------------------------------------------------------------
// Kernel 3: combine d-halves + softmax.
// ---------------------------------------------------------------------------
__global__ void __launch_bounds__(256) combine_kernel(float* __restrict__ out)
{
    const int tid  = threadIdx.x;
    const int w    = tid >> 5;
    const int lane = tid & 31;
    const int r    = blockIdx.x * 8 + w;

    const float* __restrict__ p0 = g_P + (size_t)r * NK_;
    const float* __restrict__ p1 = g_P + (size_t)(BT_ * NQ_ + r) * NK_;

    float4 a = *(const float4*)(p0 + lane * 4);
    float4 c = *(const float4*)(p1 + lane * 4);
    float4 s = make_float4(a.x + c.x, a.y + c.y, a.z + c.z, a.w + c.w);

    float m = fmaxf(fmaxf(s.x, s.y), fmaxf(s.z, s.w));
#pragma unroll
    for (int o = 16; o > 0; o >>= 1)
        m = fmaxf(m, __shfl_xor_sync(0xffffffffu, m, o));

    float4 e = make_float4(__expf(s.x - m), __expf(s.y - m),
                           __expf(s.z - m), __expf(s.w - m));
    float ssum = e.x + e.y + e.z + e.w;
#pragma unroll
    for (int o = 16; o > 0; o >>= 1)
        ssum += __shfl_xor_sync(0xffffffffu, ssum, o);

    const float rinv = 1.0f / ssum;
    float4 res = make_float4(e.x * rinv, e.y * rinv, e.z * rinv, e.w * rinv);
    *(float4*)(out + (size_t)r * NK_ + lane * 4) = res;
}

// ---------------------------------------------------------------------------
extern "C" void kernel_launch(void* const* d_in, const int* in_sizes, int n_in,
                              void* d_out, int out_size)
{
    const float* query = (const float*)d_in[0];
    const float* keys  = (const float*)d_in[1];
    const float* Wq    = (const float*)d_in[2];
    const float* Wk    = (const float*)d_in[3];
    const float* bk    = (const float*)d_in[4];
    const float* v     = (const float*)d_in[5];
    float* out = (float*)d_out;

    proj_kernel<<<288, 256>>>(query, keys, Wq, Wk, bk);
    attn_partial_kernel<<<512, 256>>>(v);
    combine_kernel<<<256, 256>>>(out);
}

// round 11
// speedup vs baseline: 1.4298x; 1.4298x over previous
#include <cuda_runtime.h>
#include <cuda_fp16.h>

// Problem constants
#define B_   2
#define T_   8
#define BT_  16
#define NQ_  128
#define NK_  128
#define DIN_ 64
#define DOUT_ 256
#define DP_  128     // d-pairs (DOUT_/2), half2-packed along d
#define DPC_ 64      // d-pairs per staged chunk
#define KPITCH_ 68   // unused pitch const kept for reference

// Projected Q/K in half2 (packed d-pairs). Device globals = legal scratch.
__device__ __half2 g_Qh[B_ * NQ_ * DP_];     // 256 rows x 128 half2
__device__ __half2 g_Kh[BT_ * NK_ * DP_];    // 2048 rows x 128 half2

__device__ __forceinline__ __half2 h2tanh_mufu(__half2 x) {
    __half2 r;
    asm("tanh.approx.f16x2 %0, %1;"
        : "=r"(*reinterpret_cast<unsigned*>(&r))
        : "r"(*reinterpret_cast<unsigned*>(&x)));
    return r;
}

// ---------------------------------------------------------------------------
// Kernel 1: projections (fp32 math, half2 output), smem-staged W.
// Grid = 16 Q-blocks + 128 K-blocks = 144 x 512 thr (16 rows/block, 1/SM).
// W staged in 2 chunks of 32 rows (32KB smem) via coalesced LDG; inner loop
// reads W with conflict-free LDS.128 and x with broadcast LDS.32.
// Floors/SM: FFMA 4K cyc, LSU ~5K cyc -> ~2.5-3us (vs 7.5 latency-bound).
// ---------------------------------------------------------------------------
__global__ void __launch_bounds__(512, 1) proj_kernel(
    const float* __restrict__ query, const float* __restrict__ keys,
    const float* __restrict__ Wq,    const float* __restrict__ Wk,
    const float* __restrict__ bk)
{
    __shared__ float w_sh[32][DOUT_];       // 32 KB W chunk
    __shared__ float in_sh[16][DIN_];       // 4 KB input rows

    const int blk = blockIdx.x;             // 0..143 (16 Q, 128 K)
    const bool isQ = (blk < 16);
    const int r0 = (isQ ? blk : (blk - 16)) * 16;
    const float* __restrict__ in = isQ ? query : keys;
    const float* __restrict__ W  = isQ ? Wq    : Wk;
    __half2* __restrict__ outb   = isQ ? g_Qh  : g_Kh;

    const int tid = threadIdx.x;
    const int cg = tid & 63;                // cols 4*cg..4*cg+3
    const int rg = tid >> 6;                // row group 0..7 -> rows 2rg,2rg+1
    const int row0 = rg * 2, row1 = rg * 2 + 1;

    // Stage the 16 input rows (256 float4, half the threads)
    if (tid < 256) {
        const int r = tid >> 4, s = tid & 15;
        *(float4*)&in_sh[r][s * 4] =
            *(const float4*)(in + (size_t)(r0 + r) * DIN_ + s * 4);
    }

    float4 bias = make_float4(0.f, 0.f, 0.f, 0.f);
    if (!isQ) bias = *(const float4*)(bk + cg * 4);
    float4 acc0 = bias, acc1 = bias;

#pragma unroll 1
    for (int kc = 0; kc < 2; kc++) {
        // Cooperative W chunk load: 32 rows x 256 cols = 2048 float4,
        // 4 per thread, coalesced.
        __syncthreads();
#pragma unroll
        for (int j = 0; j < 4; j++) {
            const int f4 = tid + j * 512;           // float4 index 0..2047
            *(float4*)&w_sh[0][f4 * 4] =
                *(const float4*)(W + (size_t)(kc * 32) * DOUT_ + f4 * 4);
        }
        __syncthreads();

#pragma unroll 4
        for (int i = 0; i < 32; i++) {
            const float4 wv = *(const float4*)&w_sh[i][cg * 4];   // LDS.128
            const float x0 = in_sh[row0][kc * 32 + i];            // bcast
            const float x1 = in_sh[row1][kc * 32 + i];            // bcast
            acc0.x = fmaf(x0, wv.x, acc0.x);
            acc0.y = fmaf(x0, wv.y, acc0.y);
            acc0.z = fmaf(x0, wv.z, acc0.z);
            acc0.w = fmaf(x0, wv.w, acc0.w);
            acc1.x = fmaf(x1, wv.x, acc1.x);
            acc1.y = fmaf(x1, wv.y, acc1.y);
            acc1.z = fmaf(x1, wv.z, acc1.z);
            acc1.w = fmaf(x1, wv.w, acc1.w);
        }
    }

    {
        __half2 p0 = __floats2half2_rn(acc0.x, acc0.y);
        __half2 p1 = __floats2half2_rn(acc0.z, acc0.w);
        __half2* dst = outb + (size_t)(r0 + row0) * DP_ + cg * 2;
        dst[0] = p0; dst[1] = p1;
    }
    {
        __half2 p0 = __floats2half2_rn(acc1.x, acc1.y);
        __half2 p1 = __floats2half2_rn(acc1.z, acc1.w);
        __half2* dst = outb + (size_t)(r0 + row1) * DP_ + cg * 2;
        dst[0] = p0; dst[1] = p1;
    }
}

// ---------------------------------------------------------------------------
// Kernel 2: scores + fused softmax, half2 datapath (R3 exact — 23.87us).
// Grid 256 x 256 thr. Warp w -> query row q0+w; lane l -> nk {l,l+32,l+64,l+96}.
// K chunk (128 nk x 64 dpairs, pitch 65 half2 -> conflict-free LDS.32).
// tanh.approx.f16x2 (MUFU wall). HFMA2 accumulate, fp32 flush every 8 dp.
// ---------------------------------------------------------------------------
__global__ void __launch_bounds__(256) attn_kernel(
    const float* __restrict__ v, float* __restrict__ out)
{
    __shared__ __half2 k_sh[NK_ * (DPC_ + 1)];   // [nk][dp], pitch 65
    __shared__ __half2 q_sh[8][DPC_];
    __shared__ __half2 v_sh[DPC_];

    const int bt = blockIdx.x >> 4;
    const int q0 = (blockIdx.x & 15) << 3;
    const int b  = bt >> 3;

    const int tid  = threadIdx.x;
    const int w    = tid >> 5;
    const int lane = tid & 31;

    const __half2* __restrict__ kbase = g_Kh + (size_t)(bt * NK_) * DP_;
    const __half2* __restrict__ qbase = g_Qh + (size_t)(b * NQ_ + q0) * DP_;

    float acc0 = 0.f, acc1 = 0.f, acc2 = 0.f, acc3 = 0.f;

#pragma unroll 1
    for (int c = 0; c < DP_ / DPC_; c++) {
        const int d0 = c * DPC_;

        // Stage K chunk: 128 rows x 16 uint4 (8 per thread)
#pragma unroll
        for (int e = tid; e < NK_ * 16; e += 256) {
            const int nk = e >> 4, s = e & 15;
            uint4 t = *(const uint4*)(kbase + (size_t)nk * DP_ + d0 + s * 4);
            __half2* dst = &k_sh[nk * (DPC_ + 1) + s * 4];
            *(unsigned*)&dst[0] = t.x;
            *(unsigned*)&dst[1] = t.y;
            *(unsigned*)&dst[2] = t.z;
            *(unsigned*)&dst[3] = t.w;
        }
        // Stage Q chunk: 8 rows x 16 uint4
        if (tid < 128) {
            const int r = tid >> 4, s = tid & 15;
            *(uint4*)&q_sh[r][s * 4] =
                *(const uint4*)(qbase + (size_t)r * DP_ + d0 + s * 4);
        }
        // Stage v chunk (convert fp32 -> half2 on the fly)
        if (tid < DPC_) {
            float2 vv = *(const float2*)(v + 2 * (d0 + tid));
            v_sh[tid] = __floats2half2_rn(vv.x, vv.y);
        }
        __syncthreads();

        const __half2* __restrict__ k0p = &k_sh[(lane      ) * (DPC_ + 1)];
        const __half2* __restrict__ k1p = &k_sh[(lane + 32 ) * (DPC_ + 1)];
        const __half2* __restrict__ k2p = &k_sh[(lane + 64 ) * (DPC_ + 1)];
        const __half2* __restrict__ k3p = &k_sh[(lane + 96 ) * (DPC_ + 1)];

#pragma unroll 2
        for (int dp8 = 0; dp8 < DPC_; dp8 += 8) {
            uint4 qa = *(const uint4*)&q_sh[w][dp8];
            uint4 qb4 = *(const uint4*)&q_sh[w][dp8 + 4];
            uint4 va = *(const uint4*)&v_sh[dp8];
            uint4 vb4 = *(const uint4*)&v_sh[dp8 + 4];
            unsigned qr[8] = {qa.x, qa.y, qa.z, qa.w, qb4.x, qb4.y, qb4.z, qb4.w};
            unsigned vr[8] = {va.x, va.y, va.z, va.w, vb4.x, vb4.y, vb4.z, vb4.w};

            __half2 h0 = __float2half2_rn(0.f);
            __half2 h1 = h0, h2 = h0, h3 = h0;
#pragma unroll
            for (int j = 0; j < 8; j++) {
                const int dp = dp8 + j;
                const __half2 qp = *reinterpret_cast<const __half2*>(&qr[j]);
                const __half2 vp = *reinterpret_cast<const __half2*>(&vr[j]);
                __half2 t0 = h2tanh_mufu(__hadd2(qp, k0p[dp]));
                __half2 t1 = h2tanh_mufu(__hadd2(qp, k1p[dp]));
                __half2 t2 = h2tanh_mufu(__hadd2(qp, k2p[dp]));
                __half2 t3 = h2tanh_mufu(__hadd2(qp, k3p[dp]));
                h0 = __hfma2(vp, t0, h0);
                h1 = __hfma2(vp, t1, h1);
                h2 = __hfma2(vp, t2, h2);
                h3 = __hfma2(vp, t3, h3);
            }
            float2 f0 = __half22float2(h0);
            float2 f1 = __half22float2(h1);
            float2 f2 = __half22float2(h2);
            float2 f3 = __half22float2(h3);
            acc0 += f0.x + f0.y;
            acc1 += f1.x + f1.y;
            acc2 += f2.x + f2.y;
            acc3 += f3.x + f3.y;
        }
        __syncthreads();
    }

    // Fused softmax over nk (warp owns the full 128-wide row)
    float m = fmaxf(fmaxf(acc0, acc1), fmaxf(acc2, acc3));
#pragma unroll
    for (int o = 16; o > 0; o >>= 1)
        m = fmaxf(m, __shfl_xor_sync(0xffffffffu, m, o));

    const float e0 = __expf(acc0 - m);
    const float e1 = __expf(acc1 - m);
    const float e2 = __expf(acc2 - m);
    const float e3 = __expf(acc3 - m);
    float ssum = e0 + e1 + e2 + e3;
#pragma unroll
    for (int o = 16; o > 0; o >>= 1)
        ssum += __shfl_xor_sync(0xffffffffu, ssum, o);

    const float rinv = 1.0f / ssum;

    float* __restrict__ orow = out + (size_t)(bt * NQ_ + q0 + w) * NK_;
    orow[lane      ] = e0 * rinv;
    orow[lane + 32 ] = e1 * rinv;
    orow[lane + 64 ] = e2 * rinv;
    orow[lane + 96 ] = e3 * rinv;
}

// ---------------------------------------------------------------------------
extern "C" void kernel_launch(void* const* d_in, const int* in_sizes, int n_in,
                              void* d_out, int out_size)
{
    const float* query = (const float*)d_in[0];
    const float* keys  = (const float*)d_in[1];
    const float* Wq    = (const float*)d_in[2];
    const float* Wk    = (const float*)d_in[3];
    const float* bk    = (const float*)d_in[4];
    const float* v     = (const float*)d_in[5];
    float* out = (float*)d_out;

    proj_kernel<<<144, 512>>>(query, keys, Wq, Wk, bk);
    attn_kernel<<<256, 256>>>(v, out);
}

// round 12
// speedup vs baseline: 1.4314x; 1.0011x over previous
#include <cuda_runtime.h>
#include <cuda_fp16.h>

// Problem constants
#define B_   2
#define T_   8
#define BT_  16
#define NQ_  128
#define NK_  128
#define DIN_ 64
#define DOUT_ 256
#define DP_  128     // d-pairs total (DOUT_/2)
#define DPC2_ 32     // d-pairs per staged chunk (4 chunks)
#define P16_ 33      // k16 row pitch in half2 words (odd -> conflict-free LDS.32)
#define PT_  68      // kt row pitch in float words (68%32==4 -> conflict-free LDS.128)

// Device-global scratch
__device__ __half2 g_Qh[B_ * NQ_ * DP_];      // raw proj Q, half2 (MUFU path)
__device__ __half2 g_Kh[BT_ * NK_ * DP_];     // raw proj K, half2 (MUFU path)
__device__ float   g_Qt[B_ * NQ_ * DOUT_];    // tanh(proj Q), fp32 (identity path)
__device__ float   g_Kt[BT_ * NK_ * DOUT_];   // tanh(proj K), fp32 (identity path)

__device__ __forceinline__ __half2 h2tanh_mufu(__half2 x) {
    __half2 r;
    asm("tanh.approx.f16x2 %0, %1;"
        : "=r"(*reinterpret_cast<unsigned*>(&r))
        : "r"(*reinterpret_cast<unsigned*>(&x)));
    return r;
}
__device__ __forceinline__ float ftanh(float x) {
    float r;
    asm("tanh.approx.f32 %0, %1;" : "=f"(r) : "f"(x));
    return r;
}

// Exact tanh addition identity, FMA-pipe only (no MUFU):
//   tanh(q+k) = (tq+tk) / (1+tq*tk); reciprocal via magic seed + 3 Newton.
// den = 1 + tq*tk in (0,2): always positive normal float.
#define IDENT_ACC(tq, tk, vd, acc) do {                                   \
    const float den_ = fmaf((tq), (tk), 1.0f);                            \
    const float num_ = (tq) + (tk);                                       \
    float y_ = __int_as_float(0x7EF311C3 - __float_as_int(den_));         \
    y_ = y_ * fmaf(-den_, y_, 2.0f);                                      \
    y_ = y_ * fmaf(-den_, y_, 2.0f);                                      \
    y_ = y_ * fmaf(-den_, y_, 2.0f);                                      \
    (acc) = fmaf((vd), num_ * y_, (acc));                                 \
} while (0)

// ---------------------------------------------------------------------------
// Kernel 1: projections (fp32 math), dual-format output:
//   raw half2 (for MUFU tanh streams) + fp32 tanh'd (for identity stream).
// Grid 144 x 512 thr (16 rows/block, 1/SM), W staged via smem.
// ---------------------------------------------------------------------------
__global__ void __launch_bounds__(512, 1) proj_kernel(
    const float* __restrict__ query, const float* __restrict__ keys,
    const float* __restrict__ Wq,    const float* __restrict__ Wk,
    const float* __restrict__ bk)
{
    __shared__ float w_sh[32][DOUT_];       // 32 KB W chunk
    __shared__ float in_sh[16][DIN_];       // 4 KB input rows

    const int blk = blockIdx.x;             // 0..143 (16 Q, 128 K)
    const bool isQ = (blk < 16);
    const int r0 = (isQ ? blk : (blk - 16)) * 16;
    const float* __restrict__ in = isQ ? query : keys;
    const float* __restrict__ W  = isQ ? Wq    : Wk;
    __half2* __restrict__ outh   = isQ ? g_Qh  : g_Kh;
    float* __restrict__ outt     = isQ ? g_Qt  : g_Kt;

    const int tid = threadIdx.x;
    const int cg = tid & 63;
    const int rg = tid >> 6;
    const int row0 = rg * 2, row1 = rg * 2 + 1;

    if (tid < 256) {
        const int r = tid >> 4, s = tid & 15;
        *(float4*)&in_sh[r][s * 4] =
            *(const float4*)(in + (size_t)(r0 + r) * DIN_ + s * 4);
    }

    float4 bias = make_float4(0.f, 0.f, 0.f, 0.f);
    if (!isQ) bias = *(const float4*)(bk + cg * 4);
    float4 acc0 = bias, acc1 = bias;

#pragma unroll 1
    for (int kc = 0; kc < 2; kc++) {
        __syncthreads();
#pragma unroll
        for (int j = 0; j < 4; j++) {
            const int f4 = tid + j * 512;
            *(float4*)&w_sh[0][f4 * 4] =
                *(const float4*)(W + (size_t)(kc * 32) * DOUT_ + f4 * 4);
        }
        __syncthreads();

#pragma unroll 4
        for (int i = 0; i < 32; i++) {
            const float4 wv = *(const float4*)&w_sh[i][cg * 4];
            const float x0 = in_sh[row0][kc * 32 + i];
            const float x1 = in_sh[row1][kc * 32 + i];
            acc0.x = fmaf(x0, wv.x, acc0.x);
            acc0.y = fmaf(x0, wv.y, acc0.y);
            acc0.z = fmaf(x0, wv.z, acc0.z);
            acc0.w = fmaf(x0, wv.w, acc0.w);
            acc1.x = fmaf(x1, wv.x, acc1.x);
            acc1.y = fmaf(x1, wv.y, acc1.y);
            acc1.z = fmaf(x1, wv.z, acc1.z);
            acc1.w = fmaf(x1, wv.w, acc1.w);
        }
    }

    // raw half2
    {
        __half2 p0 = __floats2half2_rn(acc0.x, acc0.y);
        __half2 p1 = __floats2half2_rn(acc0.z, acc0.w);
        __half2* dst = outh + (size_t)(r0 + row0) * DP_ + cg * 2;
        dst[0] = p0; dst[1] = p1;
    }
    {
        __half2 p0 = __floats2half2_rn(acc1.x, acc1.y);
        __half2 p1 = __floats2half2_rn(acc1.z, acc1.w);
        __half2* dst = outh + (size_t)(r0 + row1) * DP_ + cg * 2;
        dst[0] = p0; dst[1] = p1;
    }
    // tanh'd fp32
    {
        float4 t = make_float4(ftanh(acc0.x), ftanh(acc0.y),
                               ftanh(acc0.z), ftanh(acc0.w));
        *(float4*)&outt[(size_t)(r0 + row0) * DOUT_ + cg * 4] = t;
    }
    {
        float4 t = make_float4(ftanh(acc1.x), ftanh(acc1.y),
                               ftanh(acc1.z), ftanh(acc1.w));
        *(float4*)&outt[(size_t)(r0 + row1) * DOUT_ + cg * 4] = t;
    }
}

// ---------------------------------------------------------------------------
// Kernel 2: hybrid pipe-split scores + fused softmax.
// Grid 256 x 256 thr. Warp w -> q row q0+w. Lane l:
//   streams A/B/C -> nk {l, l+32, l+64}: f16x2 MUFU tanh (proven R3 path)
//   stream  D     -> nk l+96:            fp32 exact identity on FMA pipe
// MUFU load drops to 3/4 (31.9K cyc/SMSP); FMA pipe picks up ~25.5K. 4 chunks
// of 32 dp (64 d). Softmax fused per warp.
// ---------------------------------------------------------------------------
__global__ void __launch_bounds__(256, 2) attn_kernel(
    const float* __restrict__ v, float* __restrict__ out)
{
    __shared__ __half2 k16_sh[96 * P16_];   // 12.7 KB: nk 0..95, f16x2
    __shared__ float   kt_sh[32 * PT_];     // 8.7 KB : nk 96..127, fp32 tanh'd
    __shared__ __half2 q16_sh[8][DPC2_];    // 1 KB
    __shared__ float   qt_sh[8][2 * DPC2_]; // 2 KB
    __shared__ __half2 v16_sh[DPC2_];       // 128 B
    __shared__ float   vt_sh[2 * DPC2_];    // 256 B

    const int bt = blockIdx.x >> 4;
    const int q0 = (blockIdx.x & 15) << 3;
    const int b  = bt >> 3;

    const int tid  = threadIdx.x;
    const int w    = tid >> 5;
    const int lane = tid & 31;

    const __half2* __restrict__ khbase = g_Kh + (size_t)(bt * NK_) * DP_;
    const __half2* __restrict__ qhbase = g_Qh + (size_t)(b * NQ_ + q0) * DP_;
    const float*   __restrict__ ktbase = g_Kt + (size_t)(bt * NK_ + 96) * DOUT_;
    const float*   __restrict__ qtbase = g_Qt + (size_t)(b * NQ_ + q0) * DOUT_;

    float acc0 = 0.f, acc1 = 0.f, acc2 = 0.f, acc3 = 0.f;

#pragma unroll 1
    for (int c = 0; c < DP_ / DPC2_; c++) {
        const int d0dp = c * DPC2_;          // dp offset
        const int d0   = c * 2 * DPC2_;      // d offset

        // Stage k16: 96 rows x 8 uint4 (3 per thread); scalar STS (odd pitch)
#pragma unroll
        for (int e = tid; e < 96 * 8; e += 256) {
            const int nk = e >> 3, s = e & 7;
            uint4 t = *(const uint4*)(khbase + (size_t)nk * DP_ + d0dp + s * 4);
            __half2* dst = &k16_sh[nk * P16_ + s * 4];
            *(unsigned*)&dst[0] = t.x;
            *(unsigned*)&dst[1] = t.y;
            *(unsigned*)&dst[2] = t.z;
            *(unsigned*)&dst[3] = t.w;
        }
        // Stage kt: 32 rows x 16 float4 (2 per thread), pitch 68 (aligned)
#pragma unroll
        for (int e = tid; e < 32 * 16; e += 256) {
            const int nk = e >> 4, s = e & 15;
            float4 t = *(const float4*)(ktbase + (size_t)nk * DOUT_ + d0 + s * 4);
            *(float4*)&kt_sh[nk * PT_ + s * 4] = t;
        }
        // Stage q16: 8 rows x 8 uint4
        if (tid < 64) {
            const int r = tid >> 3, s = tid & 7;
            *(uint4*)&q16_sh[r][s * 4] =
                *(const uint4*)(qhbase + (size_t)r * DP_ + d0dp + s * 4);
        }
        // Stage qt: 8 rows x 16 float4
        if (tid >= 64 && tid < 192) {
            const int e = tid - 64;
            const int r = e >> 4, s = e & 15;
            *(float4*)&qt_sh[r][s * 4] =
                *(const float4*)(qtbase + (size_t)r * DOUT_ + d0 + s * 4);
        }
        // Stage v16 (fp32 -> half2) and vt (fp32)
        if (tid >= 192 && tid < 224) {
            const int i = tid - 192;
            float2 vv = *(const float2*)(v + d0 + 2 * i);
            v16_sh[i] = __floats2half2_rn(vv.x, vv.y);
        }
        if (tid >= 224 && tid < 240) {
            const int s = tid - 224;
            *(float4*)&vt_sh[s * 4] = *(const float4*)(v + d0 + s * 4);
        }
        __syncthreads();

        const __half2* __restrict__ k0p = &k16_sh[(lane      ) * P16_];
        const __half2* __restrict__ k1p = &k16_sh[(lane + 32 ) * P16_];
        const __half2* __restrict__ k2p = &k16_sh[(lane + 64 ) * P16_];
        const float*   __restrict__ kDp = &kt_sh[lane * PT_];

#pragma unroll 2
        for (int dp8 = 0; dp8 < DPC2_; dp8 += 8) {
            // ---- f16x2 MUFU streams A, B, C ----
            uint4 qa = *(const uint4*)&q16_sh[w][dp8];
            uint4 qb4 = *(const uint4*)&q16_sh[w][dp8 + 4];
            uint4 va = *(const uint4*)&v16_sh[dp8];
            uint4 vb4 = *(const uint4*)&v16_sh[dp8 + 4];
            unsigned qr[8] = {qa.x, qa.y, qa.z, qa.w, qb4.x, qb4.y, qb4.z, qb4.w};
            unsigned vr[8] = {va.x, va.y, va.z, va.w, vb4.x, vb4.y, vb4.z, vb4.w};

            __half2 h0 = __float2half2_rn(0.f);
            __half2 h1 = h0, h2 = h0;
#pragma unroll
            for (int j = 0; j < 8; j++) {
                const int dp = dp8 + j;
                const __half2 qp = *reinterpret_cast<const __half2*>(&qr[j]);
                const __half2 vp = *reinterpret_cast<const __half2*>(&vr[j]);
                __half2 t0 = h2tanh_mufu(__hadd2(qp, k0p[dp]));
                __half2 t1 = h2tanh_mufu(__hadd2(qp, k1p[dp]));
                __half2 t2 = h2tanh_mufu(__hadd2(qp, k2p[dp]));
                h0 = __hfma2(vp, t0, h0);
                h1 = __hfma2(vp, t1, h1);
                h2 = __hfma2(vp, t2, h2);
            }
            float2 f0 = __half22float2(h0);
            float2 f1 = __half22float2(h1);
            float2 f2 = __half22float2(h2);
            acc0 += f0.x + f0.y;
            acc1 += f1.x + f1.y;
            acc2 += f2.x + f2.y;

            // ---- fp32 identity stream D (FMA pipe only): d = 2*dp8 .. +15 ----
            const int dd = 2 * dp8;
#pragma unroll
            for (int p4 = 0; p4 < 4; p4++) {
                const float4 kD = *(const float4*)(kDp + dd + p4 * 4);
                const float4 qD = *(const float4*)&qt_sh[w][dd + p4 * 4];
                const float4 vD = *(const float4*)&vt_sh[dd + p4 * 4];
                IDENT_ACC(qD.x, kD.x, vD.x, acc3);
                IDENT_ACC(qD.y, kD.y, vD.y, acc3);
                IDENT_ACC(qD.z, kD.z, vD.z, acc3);
                IDENT_ACC(qD.w, kD.w, vD.w, acc3);
            }
        }
        __syncthreads();
    }

    // Fused softmax over nk (warp owns the full 128-wide row)
    float m = fmaxf(fmaxf(acc0, acc1), fmaxf(acc2, acc3));
#pragma unroll
    for (int o = 16; o > 0; o >>= 1)
        m = fmaxf(m, __shfl_xor_sync(0xffffffffu, m, o));

    const float e0 = __expf(acc0 - m);
    const float e1 = __expf(acc1 - m);
    const float e2 = __expf(acc2 - m);
    const float e3 = __expf(acc3 - m);
    float ssum = e0 + e1 + e2 + e3;
#pragma unroll
    for (int o = 16; o > 0; o >>= 1)
        ssum += __shfl_xor_sync(0xffffffffu, ssum, o);

    const float rinv = 1.0f / ssum;

    float* __restrict__ orow = out + (size_t)(bt * NQ_ + q0 + w) * NK_;
    orow[lane      ] = e0 * rinv;
    orow[lane + 32 ] = e1 * rinv;
    orow[lane + 64 ] = e2 * rinv;
    orow[lane + 96 ] = e3 * rinv;
}

// ---------------------------------------------------------------------------
extern "C" void kernel_launch(void* const* d_in, const int* in_sizes, int n_in,
                              void* d_out, int out_size)
{
    const float* query = (const float*)d_in[0];
    const float* keys  = (const float*)d_in[1];
    const float* Wq    = (const float*)d_in[2];
    const float* Wk    = (const float*)d_in[3];
    const float* bk    = (const float*)d_in[4];
    const float* v     = (const float*)d_in[5];
    float* out = (float*)d_out;

    proj_kernel<<<144, 512>>>(query, keys, Wq, Wk, bk);
    attn_kernel<<<256, 256>>>(v, out);
}